// round 10
// baseline (speedup 1.0000x reference)
#include <cuda_runtime.h>
#include <cstdint>

// RegressionLoss: masked SmoothL1 (beta=0.5) sum over N=16,777,216.
//   d = outs - labels; ad = |d|
//   sl1 = ad < 0.5 ? d*d : ad - 0.25
//   keep if ad >= 1/len  (lens int32 on device; JAX x64 off)
//   out[0] = sum(keep ? sl1 : 0)
//
// R7 (occ 8, 3x LDG.128/iter, grid 2368): 32.3us kernel, DRAM=80.3%.
// R9 (occ 6, unroll-2, single wave): 35.6us, DRAM=72.7% -> REVERTED.
// This round = R7 mainloop + fused last-block finalize (no zero kernel).

#define MAXBLOCKS 2368       // 148 SMs * occ 8 -> exactly two waves
#define NTHREADS 256

__device__ float    g_partial[MAXBLOCKS];
__device__ unsigned g_count;   // zero at module load; self-resets each call

__device__ __forceinline__ float sl1_masked(float o, float l, float lenf) {
    float d  = o - l;
    float ad = fabsf(d);
    float v  = (ad < 0.5f) ? (d * d) : (ad - 0.25f);
    // ad >= 1/len  <=>  ad*len >= 1  (len in [1,1000]; ~1ulp edge noise)
    return (ad * lenf >= 1.0f) ? v : 0.0f;
}

__global__ __launch_bounds__(NTHREADS, 8)
void smoothl1_masked_sum_kernel(const float4* __restrict__ outs4,
                                const float4* __restrict__ labels4,
                                const int4*   __restrict__ lens4,
                                const float*  __restrict__ outs,
                                const float*  __restrict__ labels,
                                const int*    __restrict__ lens,
                                float* __restrict__ out,
                                int nvec, int n, int nblocks) {
    float acc = 0.0f;
    const int stride = gridDim.x * blockDim.x;
    int i = blockIdx.x * blockDim.x + threadIdx.x;

    for (; i < nvec; i += stride) {
        float4 o = outs4[i];
        float4 l = labels4[i];
        int4   L = lens4[i];
        acc += sl1_masked(o.x, l.x, (float)L.x);
        acc += sl1_masked(o.y, l.y, (float)L.y);
        acc += sl1_masked(o.z, l.z, (float)L.z);
        acc += sl1_masked(o.w, l.w, (float)L.w);
    }

    // scalar tail (n not divisible by 4)
    int t = nvec * 4 + blockIdx.x * blockDim.x + threadIdx.x;
    if (t < n) acc += sl1_masked(outs[t], labels[t], (float)lens[t]);

    // ---- block reduction ----
    #pragma unroll
    for (int off = 16; off > 0; off >>= 1)
        acc += __shfl_xor_sync(0xffffffffu, acc, off);

    __shared__ float warp_sums[8];
    __shared__ bool  is_last;
    int lane = threadIdx.x & 31;
    int wid  = threadIdx.x >> 5;
    if (lane == 0) warp_sums[wid] = acc;
    __syncthreads();

    if (wid == 0) {
        float v = (lane < 8) ? warp_sums[lane] : 0.0f;
        #pragma unroll
        for (int off = 4; off > 0; off >>= 1)
            v += __shfl_xor_sync(0xffffffffu, v, off);
        if (lane == 0) {
            g_partial[blockIdx.x] = v;
            __threadfence();
            unsigned prev = atomicAdd(&g_count, 1u);
            is_last = (prev == (unsigned)(nblocks - 1));
        }
    }
    __syncthreads();

    // ---- last block finalizes ----
    if (is_last) {
        __threadfence();
        float s = 0.0f;
        for (int j = threadIdx.x; j < nblocks; j += blockDim.x)
            s += g_partial[j];
        #pragma unroll
        for (int off = 16; off > 0; off >>= 1)
            s += __shfl_xor_sync(0xffffffffu, s, off);
        if (lane == 0) warp_sums[wid] = s;
        __syncthreads();
        if (wid == 0) {
            float v = (lane < 8) ? warp_sums[lane] : 0.0f;
            #pragma unroll
            for (int off = 4; off > 0; off >>= 1)
                v += __shfl_xor_sync(0xffffffffu, v, off);
            if (lane == 0) {
                out[0]  = v;
                g_count = 0u;   // reset for next graph replay
            }
        }
    }
}

extern "C" void kernel_launch(void* const* d_in, const int* in_sizes, int n_in,
                              void* d_out, int out_size) {
    const float* outs   = (const float*)d_in[0];
    const float* labels = (const float*)d_in[1];
    const int*   lens   = (const int*)d_in[2];
    float* out = (float*)d_out;
    const int n    = in_sizes[0];
    const int nvec = n >> 2;

    int blocks = MAXBLOCKS;
    int max_blocks = (nvec + NTHREADS - 1) / NTHREADS;
    if (blocks > max_blocks && max_blocks > 0) blocks = max_blocks;
    if (blocks < 1) blocks = 1;

    smoothl1_masked_sum_kernel<<<blocks, NTHREADS>>>(
        (const float4*)outs, (const float4*)labels, (const int4*)lens,
        outs, labels, lens, out, nvec, n, blocks);
}

// round 12
// speedup vs baseline: 1.1980x; 1.1980x over previous
#include <cuda_runtime.h>
#include <cstdint>

// RegressionLoss: masked SmoothL1 (beta=0.5) sum over N=16,777,216 elements.
//   d = outs - labels; ad = |d|
//   sl1 = ad < 0.5 ? d*d : ad - 0.25       (beta=0.5: 0.5*d*d/0.5 = d*d)
//   keep if ad >= 1/len
//   out[0] = sum(keep ? sl1 : 0)
//
// lens is int32 on device (JAX x64 off). Read as int4.
//
// R7 EXACT RESUBMIT — proven 33.28us total / 32.3us kernel, DRAM=80.3%
// (6.36 TB/s ~= LTS-path cap). R9 (unroll-2/occ6) and R10 (fused finalize)
// both regressed: the finalize epilogue perturbed mainloop codegen (~1.7x
// instruction count). Do not touch kernel source; only grid count is a safe
// knob.

__global__ void zero_out_kernel(float* __restrict__ out) {
    if (threadIdx.x == 0) out[0] = 0.0f;
}

__device__ __forceinline__ float sl1_masked(float o, float l, float lenf) {
    float d  = o - l;
    float ad = fabsf(d);
    float v  = (ad < 0.5f) ? (d * d) : (ad - 0.25f);
    // mask: ad >= 1/len  <=>  ad*len >= 1 (len in [1,1000]; edge noise ~1ulp)
    return (ad * lenf >= 1.0f) ? v : 0.0f;
}

__global__ __launch_bounds__(256, 8)
void smoothl1_masked_sum_kernel(const float4* __restrict__ outs4,
                                const float4* __restrict__ labels4,
                                const int4*   __restrict__ lens4,
                                const float*  __restrict__ outs,
                                const float*  __restrict__ labels,
                                const int*    __restrict__ lens,
                                float* __restrict__ out,
                                int nvec, int n) {
    float acc = 0.0f;
    const int stride = gridDim.x * blockDim.x;
    int i = blockIdx.x * blockDim.x + threadIdx.x;

    for (; i < nvec; i += stride) {
        float4 o = outs4[i];
        float4 l = labels4[i];
        int4   L = lens4[i];
        acc += sl1_masked(o.x, l.x, (float)L.x);
        acc += sl1_masked(o.y, l.y, (float)L.y);
        acc += sl1_masked(o.z, l.z, (float)L.z);
        acc += sl1_masked(o.w, l.w, (float)L.w);
    }

    // scalar tail (n not divisible by 4)
    int t = nvec * 4 + blockIdx.x * blockDim.x + threadIdx.x;
    if (t < n) {
        acc += sl1_masked(outs[t], labels[t], (float)lens[t]);
    }

    // warp reduce
    #pragma unroll
    for (int off = 16; off > 0; off >>= 1)
        acc += __shfl_xor_sync(0xffffffffu, acc, off);

    __shared__ float warp_sums[8];
    int lane = threadIdx.x & 31;
    int wid  = threadIdx.x >> 5;
    if (lane == 0) warp_sums[wid] = acc;
    __syncthreads();

    if (wid == 0) {
        float v = (lane < 8) ? warp_sums[lane] : 0.0f;
        #pragma unroll
        for (int off = 4; off > 0; off >>= 1)
            v += __shfl_xor_sync(0xffffffffu, v, off);
        if (lane == 0) atomicAdd(out, v);
    }
}

extern "C" void kernel_launch(void* const* d_in, const int* in_sizes, int n_in,
                              void* d_out, int out_size) {
    const float* outs   = (const float*)d_in[0];
    const float* labels = (const float*)d_in[1];
    const int*   lens   = (const int*)d_in[2];   // int32 on device (JAX x64 off)
    float* out = (float*)d_out;
    const int n    = in_sizes[0];
    const int nvec = n >> 2;

    zero_out_kernel<<<1, 32>>>(out);

    const int threads = 256;
    int blocks = 148 * 16;   // ~606k threads, ~7 float4 iters each
    int max_blocks = (nvec + threads - 1) / threads;
    if (blocks > max_blocks && max_blocks > 0) blocks = max_blocks;
    if (blocks < 1) blocks = 1;

    smoothl1_masked_sum_kernel<<<blocks, threads>>>(
        (const float4*)outs, (const float4*)labels, (const int4*)lens,
        outs, labels, lens, out, nvec, n);
}